// round 6
// baseline (speedup 1.0000x reference)
#include <cuda_runtime.h>
#include <cstdint>

// SlidingKVQCache on GB300: out = concat over {k,v,q} of (cache shifted left 1
// token, new token appended). Caches [4,32,2048,128] fp32, tokens [4,32,1,128].
//
// Flat per-cache view (float4 units): slab = 2048*32 = 65536 = 2^16 per (b,h).
//   out[i] = cache[i + 32]                         if (i & 65535) < 65504
//   out[i] = tok[(i>>16)*32 + ((i&65535)-65504)]   otherwise (last token row)
//
// R6: FULL-occupancy persistent kernel. 405 x 3 = 1215 CTAs (~8/SM on 152 SMs),
// each block grid-strides over its cache's 8192 chunks of 1024 float4 with the
// R2 inner body (U=4 front-batched __ldcs, plain STG.128). Eliminates all wave
// transitions while keeping maximal resident warps.

static constexpr unsigned SLABMASK = 65535u;
static constexpr unsigned TAIL4    = 65504u;
static constexpr unsigned CACHE4   = 1u << 23;          // 8388608 float4 per cache

static constexpr int THREADS = 256;
static constexpr int U = 4;                             // float4 per thread
static constexpr unsigned PER_BLOCK = THREADS * U;      // 1024
static constexpr unsigned CHUNKS    = CACHE4 / PER_BLOCK; // 8192 chunks per cache
static constexpr unsigned GRID_X    = 405;              // 405*3 = 1215 CTAs ≈ 152 SMs * 8

__global__ __launch_bounds__(THREADS, 8)
void sliding_cache_persist_full_kernel(
    const float4* __restrict__ kc,
    const float4* __restrict__ vc,
    const float4* __restrict__ qc,
    const float4* __restrict__ kt,
    const float4* __restrict__ vt,
    const float4* __restrict__ qt,
    float4* __restrict__ out)
{
    const int c = blockIdx.y;
    const float4* __restrict__ cache = (c == 0) ? kc : (c == 1) ? vc : qc;
    const float4* __restrict__ tok   = (c == 0) ? kt : (c == 1) ? vt : qt;
    float4* __restrict__ ob = out + (size_t)c * CACHE4;

    for (unsigned chunk = blockIdx.x; chunk < CHUNKS; chunk += GRID_X) {
        const unsigned base = chunk * PER_BLOCK + threadIdx.x;

        unsigned idx[U];
        const float4* __restrict__ src[U];

        #pragma unroll
        for (int k = 0; k < U; k++) {
            idx[k] = base + (unsigned)k * THREADS;
            unsigned pos = idx[k] & SLABMASK;
            src[k] = (pos < TAIL4)
                   ? cache + idx[k] + 32
                   : tok + ((idx[k] >> 16) << 5) + (pos - TAIL4);
        }

        float4 v[U];
        #pragma unroll
        for (int k = 0; k < U; k++) v[k] = __ldcs(src[k]);   // front-batched x4

        #pragma unroll
        for (int k = 0; k < U; k++) ob[idx[k]] = v[k];       // plain STG.128
    }
}

extern "C" void kernel_launch(void* const* d_in, const int* in_sizes, int n_in,
                              void* d_out, int out_size)
{
    const float4* kc = (const float4*)d_in[0];
    const float4* vc = (const float4*)d_in[1];
    const float4* qc = (const float4*)d_in[2];
    const float4* kt = (const float4*)d_in[3];
    const float4* vt = (const float4*)d_in[4];
    const float4* qt = (const float4*)d_in[5];
    float4* out = (float4*)d_out;

    dim3 grid(GRID_X, 3, 1);   // 1215 CTAs — one full resident wave
    sliding_cache_persist_full_kernel<<<grid, THREADS>>>(kc, vc, qc, kt, vt, qt, out);
}